// round 17
// baseline (speedup 1.0000x reference)
#include <cuda_runtime.h>
#include <cuda_fp16.h>
#include <cstdint>

// ============================================================
// WindowAttentionGlobal — fully fused, one CTA per window,
// 3 CTAs/SM. Double-buffered K=32 weight chunk pipeline:
// every cp.async copy overlaps the previous chunk's gemm.
//   prep  : W_kv/W_proj -> fp16 transposed; bias table [4][49][64]
//   fused : x->fp16 -> kv GEMM (8 chunks) -> attention -> proj (4 chunks)
// ============================================================

#define NWIN   49
#define DIMC   128
#define HEADS  4
#define SCALE  0.17677669529663689f

__device__ __half g_wkvT[256 * 128];     // [n][k]
__device__ __half g_wprojT[128 * 128];   // [n][k]
__device__ float  g_bias[4 * 49 * 64];   // [h][r][c], c>=49 -> -1e9

extern __shared__ char dynsmem[];

// smem layout (halves):
//   As  [64][136]      @0      17408 B  (x tile -> later o tile)
//   B0  [128][40]      @8704   10240 B  (weight chunk buffer 0)
//   B1  [128][40]      @13824  10240 B  (weight chunk buffer 1)
//   kvs [64][264]      @18944  33792 B  (kv tile; later fp32 out [64][132])
#define F_B0 8704
#define F_B1 13824
#define F_KV 18944
#define FU_SMEM ((18944 + 16896) * 2)    // 71680 B

__device__ __forceinline__ uint32_t smem_u32(const void* p) {
    uint32_t a;
    asm("{ .reg .u64 t; cvta.to.shared.u64 t, %1; cvt.u32.u64 %0, t; }" : "=r"(a) : "l"(p));
    return a;
}
__device__ __forceinline__ uint32_t h2u(__half2 h) { return *reinterpret_cast<uint32_t*>(&h); }

#define LDSM_X4(r, addr)                                                      \
    asm volatile("ldmatrix.sync.aligned.m8n8.x4.shared.b16 {%0,%1,%2,%3}, [%4];" \
                 : "=r"((r)[0]), "=r"((r)[1]), "=r"((r)[2]), "=r"((r)[3]) : "r"(addr))
#define LDSM_X4_T(r, addr)                                                    \
    asm volatile("ldmatrix.sync.aligned.m8n8.x4.trans.shared.b16 {%0,%1,%2,%3}, [%4];" \
                 : "=r"((r)[0]), "=r"((r)[1]), "=r"((r)[2]), "=r"((r)[3]) : "r"(addr))

__device__ __forceinline__ void mma16816(float* d, const uint32_t* a,
                                         uint32_t b0, uint32_t b1) {
    asm volatile(
        "mma.sync.aligned.m16n8k16.row.col.f32.f16.f16.f32 "
        "{%0,%1,%2,%3}, {%4,%5,%6,%7}, {%8,%9}, {%0,%1,%2,%3};"
        : "+f"(d[0]), "+f"(d[1]), "+f"(d[2]), "+f"(d[3])
        : "r"(a[0]), "r"(a[1]), "r"(a[2]), "r"(a[3]), "r"(b0), "r"(b1));
}

__device__ __forceinline__ void cp16(uint32_t saddr, const void* g) {
    asm volatile("cp.async.cg.shared.global [%0], [%1], 16;" :: "r"(saddr), "l"(g));
}
#define CP_COMMIT() asm volatile("cp.async.commit_group;" ::: "memory")
#define CP_WAIT0()  asm volatile("cp.async.wait_group 0;" ::: "memory")
#define CP_WAIT1()  asm volatile("cp.async.wait_group 1;" ::: "memory")

__device__ __forceinline__ uint32_t ldsm_addr(uint32_t base2B, int row0, int pitch,
                                              int col0, int l) {
    int row = row0 + (l & 7) + ((l >> 3) & 1) * 8;
    int col = col0 + (l >> 4) * 8;
    return base2B + (uint32_t)(row * pitch + col) * 2u;
}

// stage one [128 n][32 k] weight chunk (src pitch 128 halves) into buf (pitch 40)
__device__ __forceinline__ void stage32(uint32_t buf, const __half* src, int t) {
    #pragma unroll
    for (int p = 0; p < 2; p++) {                 // 512 x 16B
        int i = t + p * 256;
        int row = i >> 2, c = i & 3;
        cp16(buf + (uint32_t)(row * 40 + c * 8) * 2u, src + row * 128 + c * 8);
    }
    CP_COMMIT();
}

// 64x128 GEMM over one K=32 chunk: A[64][136] cols ak0.., B[128][40]
__device__ __forceinline__ void gemm_k32(uint32_t sbA, uint32_t sbB, int ak0,
                                         int wm, int wn, int l, float acc[2][4][4]) {
    #pragma unroll
    for (int kk = 0; kk < 32; kk += 16) {
        uint32_t a[2][4], b[2][4];
        #pragma unroll
        for (int i = 0; i < 2; i++)
            LDSM_X4(a[i], ldsm_addr(sbA, wm + 16 * i, 136, ak0 + kk, l));
        #pragma unroll
        for (int g = 0; g < 2; g++)
            LDSM_X4(b[g], ldsm_addr(sbB, wn + 16 * g, 40, kk, l));
        #pragma unroll
        for (int i = 0; i < 2; i++)
            #pragma unroll
            for (int g = 0; g < 2; g++) {
                mma16816(acc[i][2 * g],     a[i], b[g][0], b[g][2]);
                mma16816(acc[i][2 * g + 1], a[i], b[g][1], b[g][3]);
            }
    }
}

__device__ __forceinline__ void zero_acc(float acc[2][4][4]) {
    #pragma unroll
    for (int i = 0; i < 2; i++)
        #pragma unroll
        for (int j = 0; j < 4; j++)
            acc[i][j][0] = acc[i][j][1] = acc[i][j][2] = acc[i][j][3] = 0.f;
}

__device__ __forceinline__ void load_q(uint32_t aq[2][4], const float* qg,
                                       int q0, int q1, int l2) {
    #pragma unroll
    for (int kh = 0; kh < 2; kh++) {
        int c = kh * 16 + l2;
        float2 v00 = *(const float2*)&qg[q0 * 32 + c];
        float2 v10 = *(const float2*)&qg[q1 * 32 + c];
        float2 v01 = *(const float2*)&qg[q0 * 32 + c + 8];
        float2 v11 = *(const float2*)&qg[q1 * 32 + c + 8];
        aq[kh][0] = h2u(__floats2half2_rn(v00.x * SCALE, v00.y * SCALE));
        aq[kh][1] = h2u(__floats2half2_rn(v10.x * SCALE, v10.y * SCALE));
        aq[kh][2] = h2u(__floats2half2_rn(v01.x * SCALE, v01.y * SCALE));
        aq[kh][3] = h2u(__floats2half2_rn(v11.x * SCALE, v11.y * SCALE));
    }
}

// chunk n source pointer: n<8 kv (pass n>>2, k (n&3)*32); n>=8 proj k (n&3)*32
__device__ __forceinline__ const __half* wsrc(int n) {
    return (n < 8) ? (g_wkvT + (size_t)(n >> 2) * 16384 + (n & 3) * 32)
                   : (g_wprojT + (n & 3) * 32);
}

// ============================================================
__global__ void prep(const float* __restrict__ Wkv, const float* __restrict__ Wp,
                     const float* __restrict__ tbl, const int* __restrict__ ridx)
{
    int idx = blockIdx.x * 256 + threadIdx.x;
    if (idx < 32768) {
        int n = idx >> 7, k = idx & 127;
        g_wkvT[idx] = __float2half(Wkv[k * 256 + n]);
    } else if (idx < 49152) {
        int i = idx - 32768, n = i >> 7, k = i & 127;
        g_wprojT[i] = __float2half(Wp[k * 128 + n]);
    } else if (idx < 49152 + 12544) {
        int i = idx - 49152;
        int h = i / 3136, r = (i % 3136) >> 6, c = i & 63;
        g_bias[i] = (c < 49) ? tbl[ridx[r * 49 + c] * 4 + h] : -1e9f;
    }
}

// ============================================================
__global__ __launch_bounds__(256, 3)
void fused(const float* __restrict__ x, const float* __restrict__ q_global,
           const float* __restrict__ bkv, const float* __restrict__ bp,
           float* __restrict__ out)
{
    __half* As  = (__half*)dynsmem;      // [64][136]
    __half* kvs = As + F_KV;             // [64][264]
    const int b = blockIdx.x, t = threadIdx.x, l = t & 31, wid = t >> 5;
    const uint32_t sbA = smem_u32(As);
    const uint32_t sbB0 = sbA + F_B0 * 2u, sbB1 = sbA + F_B1 * 2u;
    const uint32_t sbKV = sbA + F_KV * 2u;
    const int l2 = 2 * (l & 3), l4 = l >> 2;
    const int wm = (wid >> 2) * 32, wn = (wid & 3) * 32;   // GEMM warp grid 2Mx4N

    // prologue: chunks 0,1 ride under the x load
    stage32(sbB0, wsrc(0), t);
    stage32(sbB1, wsrc(1), t);

    // ---------- phase 1: x -> fp16 As ----------
    {
        const float* xrow = x + (size_t)b * NWIN * DIMC;
        for (int i = t; i < 1568; i += 256) {              // 49 rows * 32 float4
            int row = i >> 5, f4 = i & 31;
            float4 v = *(const float4*)(xrow + row * DIMC + f4 * 4);
            *(uint2*)&As[row * 136 + f4 * 4] = make_uint2(
                h2u(__floats2half2_rn(v.x, v.y)), h2u(__floats2half2_rn(v.z, v.w)));
        }
        if (t < 240) {                                     // 15 pad rows * 16 uint4
            int row = 49 + (t >> 4), c = t & 15;
            *(uint4*)&As[row * 136 + c * 8] = make_uint4(0, 0, 0, 0);
        }
    }

    float acc[2][4][4];

    // ---------- phase 2: kv GEMM, chunks 0..7 ----------
    #pragma unroll 1
    for (int pass = 0; pass < 2; pass++) {
        zero_acc(acc);
        #pragma unroll 1
        for (int ks = 0; ks < 4; ks++) {
            const int n = pass * 4 + ks;
            if (n == 0) CP_WAIT1(); else CP_WAIT0();       // chunk n landed (mine)
            __syncthreads();                               // visible + prev gemm done
            if (n + 1 < 12 && n > 0)
                stage32((n & 1) ? sbB0 : sbB1, wsrc(n + 1), t);   // next -> other buf
            gemm_k32(sbA, (n & 1) ? sbB1 : sbB0, ks * 32, wm, wn, l, acc);
        }
        // epilogue: +bias -> kvs[:, pass*128 + c]   (own rows/cols, no sync needed)
        #pragma unroll
        for (int i = 0; i < 2; i++) {
            int rA = wm + 16 * i + l4;
            #pragma unroll
            for (int j = 0; j < 4; j++) {
                int c = wn + 8 * j + l2;
                float2 bb = *(const float2*)&bkv[pass * 128 + c];
                *(__half2*)&kvs[rA * 264 + pass * 128 + c] =
                    __floats2half2_rn(acc[i][j][0] + bb.x, acc[i][j][1] + bb.y);
                *(__half2*)&kvs[(rA + 8) * 264 + pass * 128 + c] =
                    __floats2half2_rn(acc[i][j][2] + bb.x, acc[i][j][3] + bb.y);
            }
        }
    }
    // chunk 8 (proj k0) was issued at the n=7 iteration -> lands during attention

    // ---------- phase 3: attention ----------
    const int h = wid >> 1, am = (wid & 1) * 32;           // 4 heads x 2 row-halves
    const float* qg = q_global + ((size_t)(b >> 6) * HEADS + h) * (NWIN * 32);

    // hoist tile-0 q loads above the barrier (latency absorbed by the wait)
    uint32_t aqp[2][4];
    {
        const int rA = am + l4, rB = rA + 8;
        load_q(aqp, qg, (rA < 49) ? rA : 48, (rB < 49) ? rB : 48, l2);
    }
    __syncthreads();                                       // kvs complete everywhere

    #pragma unroll 1
    for (int i = 0; i < 2; i++) {
        const int rA = am + 16 * i + l4, rB = rA + 8;
        const int q0 = (rA < 49) ? rA : 48, q1 = (rB < 49) ? rB : 48;

        uint32_t aq[2][4];
        if (i == 0) {
            #pragma unroll
            for (int kh = 0; kh < 2; kh++)
                #pragma unroll
                for (int r = 0; r < 4; r++) aq[kh][r] = aqp[kh][r];
        } else {
            load_q(aq, qg, q0, q1, l2);
        }

        // QK^T: S[16 rows][64 keys]
        float S[8][4];
        #pragma unroll
        for (int j = 0; j < 8; j++)
            S[j][0] = S[j][1] = S[j][2] = S[j][3] = 0.f;
        #pragma unroll
        for (int kh = 0; kh < 2; kh++) {
            uint32_t bk[4][4];
            #pragma unroll
            for (int g = 0; g < 4; g++)
                LDSM_X4(bk[g], ldsm_addr(sbKV, 16 * g, 264, h * 32 + kh * 16, l));
            #pragma unroll
            for (int g = 0; g < 4; g++) {
                mma16816(S[2 * g],     aq[kh], bk[g][0], bk[g][2]);
                mma16816(S[2 * g + 1], aq[kh], bk[g][1], bk[g][3]);
            }
        }

        // bias + softmax
        const float* bA = &g_bias[(h * 49 + q0) * 64];
        const float* bB = &g_bias[(h * 49 + q1) * 64];
        #pragma unroll
        for (int j = 0; j < 8; j++) {
            float2 fA = *(const float2*)&bA[8 * j + l2];
            float2 fB = *(const float2*)&bB[8 * j + l2];
            S[j][0] += fA.x; S[j][1] += fA.y;
            S[j][2] += fB.x; S[j][3] += fB.y;
        }
        float mA = -1e30f, mB = -1e30f;
        #pragma unroll
        for (int j = 0; j < 8; j++) {
            mA = fmaxf(mA, fmaxf(S[j][0], S[j][1]));
            mB = fmaxf(mB, fmaxf(S[j][2], S[j][3]));
        }
        mA = fmaxf(mA, __shfl_xor_sync(0xffffffffu, mA, 1));
        mA = fmaxf(mA, __shfl_xor_sync(0xffffffffu, mA, 2));
        mB = fmaxf(mB, __shfl_xor_sync(0xffffffffu, mB, 1));
        mB = fmaxf(mB, __shfl_xor_sync(0xffffffffu, mB, 2));
        float sA = 0.f, sB = 0.f;
        #pragma unroll
        for (int j = 0; j < 8; j++) {
            S[j][0] = __expf(S[j][0] - mA); sA += S[j][0];
            S[j][1] = __expf(S[j][1] - mA); sA += S[j][1];
            S[j][2] = __expf(S[j][2] - mB); sB += S[j][2];
            S[j][3] = __expf(S[j][3] - mB); sB += S[j][3];
        }
        sA += __shfl_xor_sync(0xffffffffu, sA, 1);
        sA += __shfl_xor_sync(0xffffffffu, sA, 2);
        sB += __shfl_xor_sync(0xffffffffu, sB, 1);
        sB += __shfl_xor_sync(0xffffffffu, sB, 2);
        const float iA = 1.f / sA, iB = 1.f / sB;

        uint32_t ph[4][4];
        #pragma unroll
        for (int tp = 0; tp < 4; tp++) {
            ph[tp][0] = h2u(__floats2half2_rn(S[2 * tp][0] * iA, S[2 * tp][1] * iA));
            ph[tp][1] = h2u(__floats2half2_rn(S[2 * tp][2] * iB, S[2 * tp][3] * iB));
            ph[tp][2] = h2u(__floats2half2_rn(S[2 * tp + 1][0] * iA, S[2 * tp + 1][1] * iA));
            ph[tp][3] = h2u(__floats2half2_rn(S[2 * tp + 1][2] * iB, S[2 * tp + 1][3] * iB));
        }

        // PV: O[16 rows][32 dims]
        float O[4][4];
        #pragma unroll
        for (int j = 0; j < 4; j++)
            O[j][0] = O[j][1] = O[j][2] = O[j][3] = 0.f;
        #pragma unroll
        for (int tp = 0; tp < 4; tp++) {
            uint32_t bv[2][4];
            #pragma unroll
            for (int g = 0; g < 2; g++)
                LDSM_X4_T(bv[g], ldsm_addr(sbKV, 16 * tp, 264, 128 + h * 32 + 16 * g, l));
            #pragma unroll
            for (int jd = 0; jd < 4; jd++) {
                int g = jd >> 1;
                if ((jd & 1) == 0) mma16816(O[jd], ph[tp], bv[g][0], bv[g][1]);
                else               mma16816(O[jd], ph[tp], bv[g][2], bv[g][3]);
            }
        }

        // stage O into As (x tile dead)
        #pragma unroll
        for (int jd = 0; jd < 4; jd++) {
            int c = h * 32 + 8 * jd + l2;
            *(__half2*)&As[rA * 136 + c] = __floats2half2_rn(O[jd][0], O[jd][1]);
            *(__half2*)&As[rB * 136 + c] = __floats2half2_rn(O[jd][2], O[jd][3]);
        }
    }

    // ---------- phase 4: proj GEMM, chunks 8..11 ----------
    zero_acc(acc);
    #pragma unroll 1
    for (int ks = 0; ks < 4; ks++) {
        const int n = 8 + ks;
        CP_WAIT0();                                        // chunk n (mine) done
        __syncthreads();                                   // visible + O staged / prev gemm done
        if (n + 1 < 12)
            stage32((n & 1) ? sbB0 : sbB1, wsrc(n + 1), t);
        gemm_k32(sbA, (n & 1) ? sbB1 : sbB0, ks * 32, wm, wn, l, acc);
    }

    // epilogue -> fp32 staging in kvs region [64][132]  (kvs data dead)
    __syncthreads();                                       // PV ldsm long done; keep order
    float* kvf = (float*)kvs;
    #pragma unroll
    for (int i = 0; i < 2; i++) {
        int rA = wm + 16 * i + l4;
        #pragma unroll
        for (int j = 0; j < 4; j++) {
            int c = wn + 8 * j + l2;
            float2 bb = *(const float2*)&bp[c];
            *(float2*)&kvf[rA * 132 + c]       = make_float2(acc[i][j][0] + bb.x, acc[i][j][1] + bb.y);
            *(float2*)&kvf[(rA + 8) * 132 + c] = make_float2(acc[i][j][2] + bb.x, acc[i][j][3] + bb.y);
        }
    }
    __syncthreads();
    float* dst = out + (size_t)b * NWIN * DIMC;
    for (int i = t; i < 1568; i += 256) {                  // 49 rows * 32 float4
        int row = i >> 5, c4 = i & 31;
        *(float4*)&dst[row * DIMC + c4 * 4] = *(const float4*)&kvf[row * 132 + c4 * 4];
    }
}

// ============================================================
extern "C" void kernel_launch(void* const* d_in, const int* in_sizes, int n_in,
                              void* d_out, int out_size)
{
    const float* x         = (const float*)d_in[0];
    const float* q_global  = (const float*)d_in[1];
    const float* tbl       = (const float*)d_in[2];
    const float* W_kv      = (const float*)d_in[3];
    const float* b_kv      = (const float*)d_in[4];
    const float* W_proj    = (const float*)d_in[5];
    const float* b_proj    = (const float*)d_in[6];
    const int*   rel_index = (const int*)d_in[7];
    float* out = (float*)d_out;

    cudaFuncSetAttribute(fused, cudaFuncAttributeMaxDynamicSharedMemorySize, FU_SMEM);

    prep <<<242, 256>>>(W_kv, W_proj, tbl, rel_index);
    fused<<<4096, 256, FU_SMEM>>>(x, q_global, b_kv, b_proj, out);
}